// round 1
// baseline (speedup 1.0000x reference)
#include <cuda_runtime.h>

#define B_    4
#define C_    128
#define H_    256
#define W_    256
#define GW    28
#define QB    784
#define Q_    3136
#define NPOS  29
#define NNEG  80
#define NOFF  109
#define ND    3136
#define NCOL  3217   /* 1 + 80 + 3136 */

static const size_t S_SCORES = (size_t)Q_ * NCOL;   // 10,088,512

// ---------------- device scratch (no allocations allowed) ----------------
__device__ float g_feat2t[(size_t)B_ * H_ * W_ * C_];   // feat2 transposed to (B,H,W,C)
__device__ float g_f1[(size_t)Q_ * C_];                 // gathered query features
__device__ float g_f2d[(size_t)ND * C_];                // gathered distractor features
__device__ int2  g_off[NOFF];                           // pos offsets then neg offsets (ref order!)
__device__ int2  g_xy2[Q_];                             // rounded flow targets

// ---------------- offsets: replicate the exact python loop order ----------------
__global__ void k_init_off() {
    if (threadIdx.x == 0 && blockIdx.x == 0) {
        int np = 0, nn = 0;
        for (int j = -49; j <= 49; j++) {
            for (int i = -49; i <= 49; i++) {
                int d2 = i * i + j * j;
                if (d2 <= 9) {                       // POS_D^2
                    g_off[np] = make_int2(i, j); np++;
                } else if (d2 >= 25 && d2 <= 49) {   // NEG_D^2 .. NGH^2
                    g_off[NPOS + nn] = make_int2(i, j); nn++;
                }
            }
        }
    }
}

// ---------------- transpose feat2 (B,C,H,W) -> (B,HW,C) ----------------
__global__ void k_transpose(const float* __restrict__ f2) {
    __shared__ float tile[32][33];
    int b  = blockIdx.z;
    int p0 = blockIdx.x * 32;     // pixel (h*W+w)
    int c0 = blockIdx.y * 32;     // channel
    int tx = threadIdx.x, ty = threadIdx.y;     // 32 x 8
    const float* src = f2 + (size_t)b * C_ * H_ * W_;
    float* dst = g_feat2t + (size_t)b * H_ * W_ * C_;
#pragma unroll
    for (int i = 0; i < 32; i += 8)
        tile[ty + i][tx] = src[(size_t)(c0 + ty + i) * (H_ * W_) + p0 + tx];
    __syncthreads();
#pragma unroll
    for (int i = 0; i < 32; i += 8)
        dst[(size_t)(p0 + ty + i) * C_ + c0 + tx] = tile[tx][ty + i];
}

// ---------------- per-query: gather f1/f2d, xy2/mask, pos+neg scores, qconf ----------------
__global__ void __launch_bounds__(128) k_posneg(const float* __restrict__ feat1,
                                                const float* __restrict__ conf1,
                                                const float* __restrict__ conf2,
                                                const float* __restrict__ aflow,
                                                float* __restrict__ out) {
    int q   = blockIdx.x;
    int tid = threadIdx.x;
    int b = q / QB;
    int r = q % QB;
    int y = 16 + (r / GW) * 8;
    int x = 16 + (r % GW) * 8;

    __shared__ __align__(16) float f1s[C_];
    __shared__ float pos_s[NPOS];
    __shared__ int2  sxy;

    // f1 gather (strided over channels) + distractor feature gather (coalesced)
    float f1v = feat1[(((size_t)b * C_ + tid) * H_ + y) * W_ + x];
    f1s[tid] = f1v;
    g_f1[(size_t)q * C_ + tid]  = f1v;
    g_f2d[(size_t)q * C_ + tid] = g_feat2t[(((size_t)b * H_ + y) * W_ + x) * C_ + tid];

    if (tid == 0) {
        float ax = aflow[(((size_t)b * 2 + 0) * H_ + y) * W_ + x];
        float ay = aflow[(((size_t)b * 2 + 1) * H_ + y) * W_ + x];
        int x2 = (int)(ax + 0.5f);   // positive values: trunc == astype(int32)
        int y2 = (int)(ay + 0.5f);
        sxy = make_int2(x2, y2);
        g_xy2[q] = sxy;
        bool m = (x2 >= 0) && (y2 >= 0) && (x2 < W_) && (y2 < H_);
        out[2 * S_SCORES + q] = m ? 1.0f : 0.0f;           // mask
    }
    __syncthreads();

    int2 xy2 = sxy;
    int lane = tid & 31, warp = tid >> 5;
    const float* f2b = g_feat2t + (size_t)b * H_ * W_ * C_;
    const float4* f1v4 = (const float4*)f1s;
    float4 a = f1v4[lane];

    for (int idx = warp; idx < NOFF; idx += 4) {
        int2 off = g_off[idx];
        int xx = min(max(xy2.x + off.x, 0), W_ - 1);
        int yy = min(max(xy2.y + off.y, 0), H_ - 1);
        const float4* p = (const float4*)(f2b + ((size_t)yy * W_ + xx) * C_);
        float4 v = p[lane];
        float s = v.x * a.x + v.y * a.y + v.z * a.z + v.w * a.w;
        s += __shfl_xor_sync(0xffffffffu, s, 16);
        s += __shfl_xor_sync(0xffffffffu, s, 8);
        s += __shfl_xor_sync(0xffffffffu, s, 4);
        s += __shfl_xor_sync(0xffffffffu, s, 2);
        s += __shfl_xor_sync(0xffffffffu, s, 1);
        if (lane == 0) {
            if (idx < NPOS) pos_s[idx] = s;
            else out[(size_t)q * NCOL + 1 + (idx - NPOS)] = s;   // nscores
        }
    }
    __syncthreads();

    if (tid == 0) {
        // first-occurrence argmax (strict > keeps first), matching jnp.argmax
        float best = pos_s[0];
        int bi = 0;
        for (int p = 1; p < NPOS; p++)
            if (pos_s[p] > best) { best = pos_s[p]; bi = p; }
        out[(size_t)q * NCOL] = best;                            // pscores
        int2 off = g_off[bi];
        int sx = min(max(xy2.x + off.x, 0), W_ - 1);
        int sy = min(max(xy2.y + off.y, 0), H_ - 1);
        float c1 = conf1[((size_t)b * H_ + y)  * W_ + x];
        float c2 = conf2[((size_t)b * H_ + sy) * W_ + sx];
        out[2 * S_SCORES + Q_ + q] = 0.5f * (c1 + c2);           // qconf
    }
}

// ---------------- dscores GEMM: (Q x 128) @ (128 x D) with distance masking ----------------
__global__ void __launch_bounds__(256) k_gemm(float* __restrict__ out) {
    __shared__ float As[32 * 65];   // As[k*65 + row]  (transposed, pad 65 => conflict-free)
    __shared__ float Bs[32 * 65];
    int q0 = blockIdx.y * 64;
    int d0 = blockIdx.x * 64;
    int t  = threadIdx.x;
    int kl = t & 31;        // k within chunk
    int rl = t >> 5;        // 0..7
    int tx = t & 15, ty = t >> 4;

    float acc[4][4] = {};

    for (int kc = 0; kc < 128; kc += 32) {
#pragma unroll
        for (int rr = rl; rr < 64; rr += 8) {
            As[kl * 65 + rr] = g_f1 [(size_t)(q0 + rr) * C_ + kc + kl];
            Bs[kl * 65 + rr] = g_f2d[(size_t)(d0 + rr) * C_ + kc + kl];
        }
        __syncthreads();
#pragma unroll
        for (int kk = 0; kk < 32; kk++) {
            float a0 = As[kk * 65 + ty * 4 + 0];
            float a1 = As[kk * 65 + ty * 4 + 1];
            float a2 = As[kk * 65 + ty * 4 + 2];
            float a3 = As[kk * 65 + ty * 4 + 3];
            float b0 = Bs[kk * 65 + tx * 4 + 0];
            float b1 = Bs[kk * 65 + tx * 4 + 1];
            float b2 = Bs[kk * 65 + tx * 4 + 2];
            float b3 = Bs[kk * 65 + tx * 4 + 3];
            acc[0][0] += a0 * b0; acc[0][1] += a0 * b1; acc[0][2] += a0 * b2; acc[0][3] += a0 * b3;
            acc[1][0] += a1 * b0; acc[1][1] += a1 * b1; acc[1][2] += a1 * b2; acc[1][3] += a1 * b3;
            acc[2][0] += a2 * b0; acc[2][1] += a2 * b1; acc[2][2] += a2 * b2; acc[2][3] += a2 * b3;
            acc[3][0] += a3 * b0; acc[3][1] += a3 * b1; acc[3][2] += a3 * b2; acc[3][3] += a3 * b3;
        }
        __syncthreads();
    }

    // epilogue: distance mask + write dscores
#pragma unroll
    for (int i = 0; i < 4; i++) {
        int q  = q0 + ty * 4 + i;
        int2 xy = g_xy2[q];
        int bq = q / QB;
#pragma unroll
        for (int j = 0; j < 4; j++) {
            int d  = d0 + tx * 4 + j;
            int b3 = d / QB;
            int rd = d % QB;
            int y3 = 16 + (rd / GW) * 8;
            int x3 = 16 + (rd % GW) * 8;
            int dx = x3 - xy.x, dy = y3 - xy.y;
            int dis2 = dx * dx + dy * dy + (b3 != bq ? 25 : 0);
            float v = (dis2 < 25) ? 0.0f : acc[i][j];
            out[(size_t)q * NCOL + 1 + NNEG + d] = v;
        }
    }
}

// ---------------- gt fill ----------------
__global__ void k_gt(float* __restrict__ out) {
    int q   = blockIdx.y;
    int col = blockIdx.x * blockDim.x + threadIdx.x;
    if (col < NCOL)
        out[S_SCORES + (size_t)q * NCOL + col] = (col == 0) ? 1.0f : 0.0f;
}

// ---------------- launch ----------------
extern "C" void kernel_launch(void* const* d_in, const int* in_sizes, int n_in,
                              void* d_out, int out_size) {
    const float* feat1 = (const float*)d_in[0];
    const float* feat2 = (const float*)d_in[1];
    const float* conf1 = (const float*)d_in[2];
    const float* conf2 = (const float*)d_in[3];
    const float* aflow = (const float*)d_in[4];
    float* out = (float*)d_out;
    (void)in_sizes; (void)n_in; (void)out_size;

    k_init_off<<<1, 32>>>();

    dim3 tb(32, 8);
    dim3 tg((H_ * W_) / 32, C_ / 32, B_);
    k_transpose<<<tg, tb>>>(feat2);

    k_posneg<<<Q_, 128>>>(feat1, conf1, conf2, aflow, out);

    dim3 gg(ND / 64, Q_ / 64);
    k_gemm<<<gg, 256>>>(out);

    k_gt<<<dim3((NCOL + 255) / 256, Q_), 256>>>(out);
}

// round 2
// speedup vs baseline: 4.3713x; 4.3713x over previous
#include <cuda_runtime.h>

#define B_    4
#define C_    128
#define H_    256
#define W_    256
#define GW    28
#define QB    784
#define Q_    3136
#define NPOS  29
#define NNEG  80
#define NOFF  109
#define ND    3136
#define NCOL  3217   /* 1 + 80 + 3136 */

static const size_t S_SCORES = (size_t)Q_ * NCOL;   // 10,088,512

// ---------------- offsets, exact reference enumeration order (j outer asc, i inner asc)
// pos: i*i+j*j <= 9 ; neg: 25 <= i*i+j*j <= 49
__constant__ int c_off[NOFF][2] = {
    // ---- 29 positives ----
    {0,-3},
    {-2,-2},{-1,-2},{0,-2},{1,-2},{2,-2},
    {-2,-1},{-1,-1},{0,-1},{1,-1},{2,-1},
    {-3,0},{-2,0},{-1,0},{0,0},{1,0},{2,0},{3,0},
    {-2,1},{-1,1},{0,1},{1,1},{2,1},
    {-2,2},{-1,2},{0,2},{1,2},{2,2},
    {0,3},
    // ---- 80 negatives ----
    {0,-7},
    {-3,-6},{-2,-6},{-1,-6},{0,-6},{1,-6},{2,-6},{3,-6},
    {-4,-5},{-3,-5},{-2,-5},{-1,-5},{0,-5},{1,-5},{2,-5},{3,-5},{4,-5},
    {-5,-4},{-4,-4},{-3,-4},{3,-4},{4,-4},{5,-4},
    {-6,-3},{-5,-3},{-4,-3},{4,-3},{5,-3},{6,-3},
    {-6,-2},{-5,-2},{5,-2},{6,-2},
    {-6,-1},{-5,-1},{5,-1},{6,-1},
    {-7,0},{-6,0},{-5,0},{5,0},{6,0},{7,0},
    {-6,1},{-5,1},{5,1},{6,1},
    {-6,2},{-5,2},{5,2},{6,2},
    {-6,3},{-5,3},{-4,3},{4,3},{5,3},{6,3},
    {-5,4},{-4,4},{-3,4},{3,4},{4,4},{5,4},
    {-4,5},{-3,5},{-2,5},{-1,5},{0,5},{1,5},{2,5},{3,5},{4,5},
    {-3,6},{-2,6},{-1,6},{0,6},{1,6},{2,6},{3,6},
    {0,7}
};

// ---------------- device scratch (no allocations allowed) ----------------
__device__ float g_feat2t[(size_t)B_ * H_ * W_ * C_];   // feat2 transposed to (B,H,W,C)
__device__ float g_f1[(size_t)Q_ * C_];                 // gathered query features
__device__ float g_f2d[(size_t)ND * C_];                // gathered distractor features
__device__ int2  g_xy2[Q_];                             // rounded flow targets

// ---------------- transpose feat2 (B,C,H,W) -> (B,HW,C) ----------------
__global__ void k_transpose(const float* __restrict__ f2) {
    __shared__ float tile[32][33];
    int b  = blockIdx.z;
    int p0 = blockIdx.x * 32;     // pixel (h*W+w)
    int c0 = blockIdx.y * 32;     // channel
    int tx = threadIdx.x, ty = threadIdx.y;     // 32 x 8
    const float* src = f2 + (size_t)b * C_ * H_ * W_;
    float* dst = g_feat2t + (size_t)b * H_ * W_ * C_;
#pragma unroll
    for (int i = 0; i < 32; i += 8)
        tile[ty + i][tx] = src[(size_t)(c0 + ty + i) * (H_ * W_) + p0 + tx];
    __syncthreads();
#pragma unroll
    for (int i = 0; i < 32; i += 8)
        dst[(size_t)(p0 + ty + i) * C_ + c0 + tx] = tile[tx][ty + i];
}

// ---------------- per-query: gather f1/f2d, xy2/mask, pos+neg scores, qconf, gt[0:81]
__global__ void __launch_bounds__(256) k_posneg(const float* __restrict__ feat1,
                                                const float* __restrict__ conf1,
                                                const float* __restrict__ conf2,
                                                const float* __restrict__ aflow,
                                                float* __restrict__ out) {
    int q   = blockIdx.x;
    int tid = threadIdx.x;
    int b = q / QB;
    int r = q % QB;
    int y = 16 + (r / GW) * 8;
    int x = 16 + (r % GW) * 8;

    __shared__ __align__(16) float f1s[C_];
    __shared__ float pos_s[NPOS];
    __shared__ int2  sxy;

    if (tid < C_) {
        // f1 gather (strided over channels) + distractor feature gather (coalesced)
        float f1v = feat1[(((size_t)b * C_ + tid) * H_ + y) * W_ + x];
        f1s[tid] = f1v;
        g_f1[(size_t)q * C_ + tid]  = f1v;
        g_f2d[(size_t)q * C_ + tid] = g_feat2t[(((size_t)b * H_ + y) * W_ + x) * C_ + tid];
    }
    if (tid < 81) {
        // gt columns 0..80 (pscores + nscores part): 1 then zeros
        out[S_SCORES + (size_t)q * NCOL + tid] = (tid == 0) ? 1.0f : 0.0f;
    }
    if (tid == 0) {
        float ax = aflow[(((size_t)b * 2 + 0) * H_ + y) * W_ + x];
        float ay = aflow[(((size_t)b * 2 + 1) * H_ + y) * W_ + x];
        int x2 = (int)(ax + 0.5f);   // inputs >= 0: trunc == astype(int32)
        int y2 = (int)(ay + 0.5f);
        sxy = make_int2(x2, y2);
        g_xy2[q] = sxy;
        bool m = (x2 >= 0) && (y2 >= 0) && (x2 < W_) && (y2 < H_);
        out[2 * S_SCORES + q] = m ? 1.0f : 0.0f;           // mask
    }
    __syncthreads();

    int2 xy2 = sxy;
    int lane = tid & 31, warp = tid >> 5;    // 8 warps
    const float* f2b = g_feat2t + (size_t)b * H_ * W_ * C_;
    const float4* f1v4 = (const float4*)f1s;
    float4 a = f1v4[lane];

    for (int idx = warp; idx < NOFF; idx += 8) {
        int ox = c_off[idx][0], oy = c_off[idx][1];
        int xx = min(max(xy2.x + ox, 0), W_ - 1);
        int yy = min(max(xy2.y + oy, 0), H_ - 1);
        const float4* p = (const float4*)(f2b + ((size_t)yy * W_ + xx) * C_);
        float4 v = p[lane];
        float s = v.x * a.x + v.y * a.y + v.z * a.z + v.w * a.w;
        s += __shfl_xor_sync(0xffffffffu, s, 16);
        s += __shfl_xor_sync(0xffffffffu, s, 8);
        s += __shfl_xor_sync(0xffffffffu, s, 4);
        s += __shfl_xor_sync(0xffffffffu, s, 2);
        s += __shfl_xor_sync(0xffffffffu, s, 1);
        if (lane == 0) {
            if (idx < NPOS) pos_s[idx] = s;
            else out[(size_t)q * NCOL + 1 + (idx - NPOS)] = s;   // nscores
        }
    }
    __syncthreads();

    if (tid == 0) {
        // first-occurrence argmax (strict > keeps first), matching jnp.argmax
        float best = pos_s[0];
        int bi = 0;
        for (int p = 1; p < NPOS; p++)
            if (pos_s[p] > best) { best = pos_s[p]; bi = p; }
        out[(size_t)q * NCOL] = best;                            // pscores
        int sx = min(max(xy2.x + c_off[bi][0], 0), W_ - 1);
        int sy = min(max(xy2.y + c_off[bi][1], 0), H_ - 1);
        float c1 = conf1[((size_t)b * H_ + y)  * W_ + x];
        float c2 = conf2[((size_t)b * H_ + sy) * W_ + sx];
        out[2 * S_SCORES + Q_ + q] = 0.5f * (c1 + c2);           // qconf
    }
}

// ---------------- dscores GEMM: (Q x 128) @ (128 x D), distance mask + gt zeros fused
#define BM 128
#define BN 128
#define BK 16
__global__ void __launch_bounds__(256) k_gemm(float* __restrict__ out) {
    __shared__ float As[BK][BM];
    __shared__ float Bs[BK][BN];
    __shared__ int   scx[BN], scy[BN], scb[BN];   // distractor coords per column
    __shared__ int   srx[BM], sry[BM], srb[BM];   // xy2 + batch per row

    int t  = threadIdx.x;
    int q0 = blockIdx.y * BM;
    int d0 = blockIdx.x * BN;
    int tx = t & 15, ty = t >> 4;

    // precompute row/col metadata
    if (t < BN) {
        int d = min(d0 + t, ND - 1);
        int b3 = d / QB, rd = d % QB;
        scb[t] = b3;
        scy[t] = 16 + (rd / GW) * 8;
        scx[t] = 16 + (rd % GW) * 8;
        int q = min(q0 + t, Q_ - 1);
        int2 xy = g_xy2[q];
        srx[t] = xy.x; sry[t] = xy.y; srb[t] = q / QB;
    }

    float acc[8][8] = {};
    int lr = t >> 2;          // 0..63
    int lk = (t & 3) * 4;     // k offset within chunk

    for (int kc = 0; kc < C_; kc += BK) {
#pragma unroll
        for (int h = 0; h < 2; h++) {
            int row = lr + h * 64;
            int gq = min(q0 + row, Q_ - 1);
            float4 v = *(const float4*)&g_f1[(size_t)gq * C_ + kc + lk];
            As[lk + 0][row] = v.x; As[lk + 1][row] = v.y;
            As[lk + 2][row] = v.z; As[lk + 3][row] = v.w;
            int gd = min(d0 + row, ND - 1);
            float4 w = *(const float4*)&g_f2d[(size_t)gd * C_ + kc + lk];
            Bs[lk + 0][row] = w.x; Bs[lk + 1][row] = w.y;
            Bs[lk + 2][row] = w.z; Bs[lk + 3][row] = w.w;
        }
        __syncthreads();
#pragma unroll
        for (int k = 0; k < BK; k++) {
            float a[8], b[8];
            *(float4*)&a[0] = *(const float4*)&As[k][ty * 4];
            *(float4*)&a[4] = *(const float4*)&As[k][64 + ty * 4];
            *(float4*)&b[0] = *(const float4*)&Bs[k][tx * 4];
            *(float4*)&b[4] = *(const float4*)&Bs[k][64 + tx * 4];
#pragma unroll
            for (int i = 0; i < 8; i++)
#pragma unroll
                for (int j = 0; j < 8; j++)
                    acc[i][j] += a[i] * b[j];
        }
        __syncthreads();
    }

    // epilogue: distance mask, dscores + gt zeros
#pragma unroll
    for (int i = 0; i < 8; i++) {
        int row = ty * 4 + (i & 3) + ((i & 4) << 4);   // +64 for i>=4
        int q = q0 + row;
        if (q >= Q_) continue;
        int qx = srx[row], qy = sry[row], qb = srb[row];
        float* so = out + (size_t)q * NCOL + 1 + NNEG;
        float* go = out + S_SCORES + (size_t)q * NCOL + 1 + NNEG;
#pragma unroll
        for (int j = 0; j < 8; j++) {
            int col = tx * 4 + (j & 3) + ((j & 4) << 4);
            int d = d0 + col;
            if (d >= ND) continue;
            int dx = scx[col] - qx, dy = scy[col] - qy;
            int dis2 = dx * dx + dy * dy + (scb[col] != qb ? 25 : 0);
            so[d] = (dis2 < 25) ? 0.0f : acc[i][j];
            go[d] = 0.0f;
        }
    }
}

// ---------------- launch ----------------
extern "C" void kernel_launch(void* const* d_in, const int* in_sizes, int n_in,
                              void* d_out, int out_size) {
    const float* feat1 = (const float*)d_in[0];
    const float* feat2 = (const float*)d_in[1];
    const float* conf1 = (const float*)d_in[2];
    const float* conf2 = (const float*)d_in[3];
    const float* aflow = (const float*)d_in[4];
    float* out = (float*)d_out;
    (void)in_sizes; (void)n_in; (void)out_size;

    dim3 tb(32, 8);
    dim3 tg((H_ * W_) / 32, C_ / 32, B_);
    k_transpose<<<tg, tb>>>(feat2);

    k_posneg<<<Q_, 256>>>(feat1, conf1, conf2, aflow, out);

    dim3 gg((ND + BN - 1) / BN, (Q_ + BM - 1) / BM);
    k_gemm<<<gg, 256>>>(out);
}

// round 3
// speedup vs baseline: 4.4230x; 1.0118x over previous
#include <cuda_runtime.h>
#include <cuda_bf16.h>
#include <cstdint>

#define B_    4
#define C_    128
#define H_    256
#define W_    256
#define GW    28
#define QB    784
#define Q_    3136
#define NPOS  29
#define NNEG  80
#define NOFF  109
#define ND    3136
#define NCOL  3217   /* 1 + 80 + 3136 */
#define MPAD  3200   /* 25 * 128 */
#define KSP   384    /* 3 * 128 : [hiA|hiA|loA] x [hiB|loB|hiB] */

static const size_t S_SCORES = (size_t)Q_ * NCOL;   // 10,088,512

// ---------------- offsets, exact reference enumeration order (j outer asc, i inner asc)
__constant__ int c_off[NOFF][2] = {
    // ---- 29 positives ----
    {0,-3},
    {-2,-2},{-1,-2},{0,-2},{1,-2},{2,-2},
    {-2,-1},{-1,-1},{0,-1},{1,-1},{2,-1},
    {-3,0},{-2,0},{-1,0},{0,0},{1,0},{2,0},{3,0},
    {-2,1},{-1,1},{0,1},{1,1},{2,1},
    {-2,2},{-1,2},{0,2},{1,2},{2,2},
    {0,3},
    // ---- 80 negatives ----
    {0,-7},
    {-3,-6},{-2,-6},{-1,-6},{0,-6},{1,-6},{2,-6},{3,-6},
    {-4,-5},{-3,-5},{-2,-5},{-1,-5},{0,-5},{1,-5},{2,-5},{3,-5},{4,-5},
    {-5,-4},{-4,-4},{-3,-4},{3,-4},{4,-4},{5,-4},
    {-6,-3},{-5,-3},{-4,-3},{4,-3},{5,-3},{6,-3},
    {-6,-2},{-5,-2},{5,-2},{6,-2},
    {-6,-1},{-5,-1},{5,-1},{6,-1},
    {-7,0},{-6,0},{-5,0},{5,0},{6,0},{7,0},
    {-6,1},{-5,1},{5,1},{6,1},
    {-6,2},{-5,2},{5,2},{6,2},
    {-6,3},{-5,3},{-4,3},{4,3},{5,3},{6,3},
    {-5,4},{-4,4},{-3,4},{3,4},{4,4},{5,4},
    {-4,5},{-3,5},{-2,5},{-1,5},{0,5},{1,5},{2,5},{3,5},{4,5},
    {-3,6},{-2,6},{-1,6},{0,6},{1,6},{2,6},{3,6},
    {0,7}
};

// ---------------- device scratch ----------------
__device__ float g_feat2t[(size_t)B_ * H_ * W_ * C_];       // feat2 -> (B,H,W,C)
__device__ __nv_bfloat16 g_a[(size_t)MPAD * KSP];           // split queries
__device__ __nv_bfloat16 g_b[(size_t)MPAD * KSP];           // split distractors
__device__ int2  g_xy2[Q_];

// ---------------- helpers ----------------
__device__ __forceinline__ void ldsm_x4(uint32_t (&r)[4], const void* p) {
    uint32_t a = (uint32_t)__cvta_generic_to_shared(p);
    asm volatile("ldmatrix.sync.aligned.m8n8.x4.shared.b16 {%0,%1,%2,%3}, [%4];"
        : "=r"(r[0]), "=r"(r[1]), "=r"(r[2]), "=r"(r[3]) : "r"(a));
}
__device__ __forceinline__ void mma_bf16(float (&d)[4], const uint32_t (&a)[4],
                                         uint32_t b0, uint32_t b1) {
    asm volatile("mma.sync.aligned.m16n8k16.row.col.f32.bf16.bf16.f32 "
        "{%0,%1,%2,%3}, {%4,%5,%6,%7}, {%8,%9}, {%0,%1,%2,%3};"
        : "+f"(d[0]), "+f"(d[1]), "+f"(d[2]), "+f"(d[3])
        : "r"(a[0]), "r"(a[1]), "r"(a[2]), "r"(a[3]), "r"(b0), "r"(b1));
}

// ---------------- transpose feat2 (B,C,H,W) -> (B,HW,C), vectorized ----------------
__global__ void __launch_bounds__(256) k_transpose(const float* __restrict__ f2) {
    __shared__ float tile[32][129];
    int b  = blockIdx.z;
    int p0 = blockIdx.x * 128;    // pixel base
    int c0 = blockIdx.y * 32;     // channel base
    int t  = threadIdx.x;
    const float* src = f2 + (size_t)b * C_ * H_ * W_;
    float* dst = g_feat2t + (size_t)b * H_ * W_ * C_;

    int px4 = t & 31;             // pixel quad
    int cy  = t >> 5;             // 0..7
#pragma unroll
    for (int k = 0; k < 4; k++) {
        int c = cy + k * 8;
        float4 v = ((const float4*)(src + (size_t)(c0 + c) * (H_ * W_) + p0))[px4];
        tile[c][px4 * 4 + 0] = v.x;
        tile[c][px4 * 4 + 1] = v.y;
        tile[c][px4 * 4 + 2] = v.z;
        tile[c][px4 * 4 + 3] = v.w;
    }
    __syncthreads();
    int p = t >> 1, h = t & 1;    // pixel, channel half (16 ch)
    float* drow = dst + (size_t)(p0 + p) * C_ + c0 + h * 16;
#pragma unroll
    for (int k = 0; k < 4; k++) {
        int cb = h * 16 + k * 4;
        float4 v = make_float4(tile[cb + 0][p], tile[cb + 1][p],
                               tile[cb + 2][p], tile[cb + 3][p]);
        ((float4*)drow)[k] = v;
    }
}

// ---------------- per-query: gathers, split operands, pos/neg scores, mask/qconf/gt[0:81]
__global__ void __launch_bounds__(128) k_posneg(const float* __restrict__ feat1,
                                                const float* __restrict__ conf1,
                                                const float* __restrict__ conf2,
                                                const float* __restrict__ aflow,
                                                float* __restrict__ out) {
    int q   = blockIdx.x;
    int tid = threadIdx.x;
    int b = q / QB;
    int r = q % QB;
    int y = 16 + (r / GW) * 8;
    int x = 16 + (r % GW) * 8;

    __shared__ __align__(16) float f1s[C_];
    __shared__ float pos_s[NPOS];
    __shared__ int2  sxy;

    // f1 gather (strided over channels)
    float f1v = feat1[(((size_t)b * C_ + tid) * H_ + y) * W_ + x];
    f1s[tid] = f1v;
    {
        __nv_bfloat16 hi = __float2bfloat16(f1v);
        __nv_bfloat16 lo = __float2bfloat16(f1v - __bfloat162float(hi));
        __nv_bfloat16* arow = g_a + (size_t)q * KSP;
        arow[tid] = hi; arow[128 + tid] = hi; arow[256 + tid] = lo;
    }
    // distractor feature gather (coalesced from transposed layout)
    {
        float f2v = g_feat2t[(((size_t)b * H_ + y) * W_ + x) * C_ + tid];
        __nv_bfloat16 hi = __float2bfloat16(f2v);
        __nv_bfloat16 lo = __float2bfloat16(f2v - __bfloat162float(hi));
        __nv_bfloat16* brow = g_b + (size_t)q * KSP;
        brow[tid] = hi; brow[128 + tid] = lo; brow[256 + tid] = hi;
    }
    if (tid < 81)   // gt columns 0..80: [1, 0 x 80]
        out[S_SCORES + (size_t)q * NCOL + tid] = (tid == 0) ? 1.0f : 0.0f;
    if (tid == 0) {
        float ax = aflow[(((size_t)b * 2 + 0) * H_ + y) * W_ + x];
        float ay = aflow[(((size_t)b * 2 + 1) * H_ + y) * W_ + x];
        int x2 = (int)(ax + 0.5f);
        int y2 = (int)(ay + 0.5f);
        sxy = make_int2(x2, y2);
        g_xy2[q] = sxy;
        bool m = (x2 >= 0) && (y2 >= 0) && (x2 < W_) && (y2 < H_);
        out[2 * S_SCORES + q] = m ? 1.0f : 0.0f;           // mask
    }
    __syncthreads();

    int2 xy2 = sxy;
    const float* f2b = g_feat2t + (size_t)b * H_ * W_ * C_;

    if (tid < NOFF) {
        int xx = min(max(xy2.x + c_off[tid][0], 0), W_ - 1);
        int yy = min(max(xy2.y + c_off[tid][1], 0), H_ - 1);
        const float4* p  = (const float4*)(f2b + ((size_t)yy * W_ + xx) * C_);
        const float4* a4 = (const float4*)f1s;
        float s = 0.0f;
#pragma unroll 8
        for (int i = 0; i < 32; i++) {
            float4 v = p[i];
            float4 a = a4[i];
            s += v.x * a.x + v.y * a.y + v.z * a.z + v.w * a.w;
        }
        if (tid < NPOS) pos_s[tid] = s;
        else out[(size_t)q * NCOL + 1 + (tid - NPOS)] = s;     // nscores
    }
    __syncthreads();

    if (tid == 0) {
        float best = pos_s[0];
        int bi = 0;
        for (int p = 1; p < NPOS; p++)
            if (pos_s[p] > best) { best = pos_s[p]; bi = p; }
        out[(size_t)q * NCOL] = best;                          // pscores
        int sx = min(max(xy2.x + c_off[bi][0], 0), W_ - 1);
        int sy = min(max(xy2.y + c_off[bi][1], 0), H_ - 1);
        float c1 = conf1[((size_t)b * H_ + y)  * W_ + x];
        float c2 = conf2[((size_t)b * H_ + sy) * W_ + sx];
        out[2 * S_SCORES + Q_ + q] = 0.5f * (c1 + c2);         // qconf
    }
}

// ---------------- dscores GEMM: bf16 tensor cores, K=384 split, mask+gt fused ----------------
__global__ void __launch_bounds__(256, 2) k_gemm(float* __restrict__ out) {
    __shared__ __nv_bfloat16 As[2][128][16];
    __shared__ __nv_bfloat16 Bs[2][128][16];
    __shared__ int scx[128], scy[128], scb[128];   // col (distractor) coords
    __shared__ int srx[128], sry[128], srb[128];   // row (query) xy2/batch

    int t  = threadIdx.x;
    int q0 = blockIdx.y * 128;
    int d0 = blockIdx.x * 128;

    if (t < 128) {
        int d = min(d0 + t, ND - 1);
        int b3 = d / QB, rd = d % QB;
        scb[t] = b3;
        scy[t] = 16 + (rd / GW) * 8;
        scx[t] = 16 + (rd % GW) * 8;
        int q = min(q0 + t, Q_ - 1);
        int2 xy = g_xy2[q];
        srx[t] = xy.x; sry[t] = xy.y; srb[t] = q / QB;
    }

    int warp = t >> 5, lane = t & 31;
    int wm = warp & 3;        // 4 warps along M (32 rows each)
    int wn = warp >> 2;       // 2 warps along N (64 cols each)
    int group = lane >> 2, tig = lane & 3;

    float acc[2][8][4];
#pragma unroll
    for (int i = 0; i < 2; i++)
#pragma unroll
        for (int j = 0; j < 8; j++)
#pragma unroll
            for (int c = 0; c < 4; c++) acc[i][j][c] = 0.0f;

    for (int kc = 0; kc < KSP; kc += 32) {
        // stage two k16 slabs of A and B
#pragma unroll
        for (int rr = 0; rr < 2; rr++) {
            int u = t + rr * 256;           // 0..511
            int row = u >> 2;
            int seg = u & 3;                // 8-element (16B) segment
            int gq = min(q0 + row, Q_ - 1);
            int gd = min(d0 + row, ND - 1);
            *(uint4*)&As[seg >> 1][row][(seg & 1) * 8] =
                *(const uint4*)&g_a[(size_t)gq * KSP + kc + seg * 8];
            *(uint4*)&Bs[seg >> 1][row][(seg & 1) * 8] =
                *(const uint4*)&g_b[(size_t)gd * KSP + kc + seg * 8];
        }
        __syncthreads();
#pragma unroll
        for (int s = 0; s < 2; s++) {
            uint32_t af[2][4], bf[4][4];
            int rsel = lane & 15;
            int csel = (lane >> 4) * 8;
#pragma unroll
            for (int i = 0; i < 2; i++)
                ldsm_x4(af[i], &As[s][wm * 32 + i * 16 + rsel][csel]);
#pragma unroll
            for (int j4 = 0; j4 < 4; j4++)
                ldsm_x4(bf[j4], &Bs[s][wn * 64 + j4 * 16 + rsel][csel]);
#pragma unroll
            for (int i = 0; i < 2; i++)
#pragma unroll
                for (int j = 0; j < 8; j++)
                    mma_bf16(acc[i][j], af[i], bf[j >> 1][j & 1], bf[j >> 1][(j & 1) + 2]);
        }
        __syncthreads();
    }

    // epilogue: distance mask -> dscores, plus gt zeros
#pragma unroll
    for (int i = 0; i < 2; i++) {
#pragma unroll
        for (int half = 0; half < 2; half++) {
            int rloc = wm * 32 + i * 16 + group + half * 8;
            int q = q0 + rloc;
            if (q >= Q_) continue;
            int qx = srx[rloc], qy = sry[rloc], qb = srb[rloc];
            float* so = out + (size_t)q * NCOL + 1 + NNEG;
            float* go = out + S_SCORES + (size_t)q * NCOL + 1 + NNEG;
#pragma unroll
            for (int j = 0; j < 8; j++) {
                int cloc = wn * 64 + j * 8 + tig * 2;
                int d = d0 + cloc;
                if (d >= ND) continue;
                int dx0 = scx[cloc] - qx,     dy0 = scy[cloc] - qy;
                int dx1 = scx[cloc + 1] - qx, dy1 = scy[cloc + 1] - qy;
                int dis0 = dx0 * dx0 + dy0 * dy0 + (scb[cloc] != qb ? 25 : 0);
                int dis1 = dx1 * dx1 + dy1 * dy1 + (scb[cloc + 1] != qb ? 25 : 0);
                so[d]     = (dis0 < 25) ? 0.0f : acc[i][j][half * 2 + 0];
                so[d + 1] = (dis1 < 25) ? 0.0f : acc[i][j][half * 2 + 1];
                go[d]     = 0.0f;
                go[d + 1] = 0.0f;
            }
        }
    }
}

// ---------------- launch ----------------
extern "C" void kernel_launch(void* const* d_in, const int* in_sizes, int n_in,
                              void* d_out, int out_size) {
    const float* feat1 = (const float*)d_in[0];
    const float* feat2 = (const float*)d_in[1];
    const float* conf1 = (const float*)d_in[2];
    const float* conf2 = (const float*)d_in[3];
    const float* aflow = (const float*)d_in[4];
    float* out = (float*)d_out;
    (void)in_sizes; (void)n_in; (void)out_size;

    dim3 tg((H_ * W_) / 128, C_ / 32, B_);
    k_transpose<<<tg, 256>>>(feat2);

    k_posneg<<<Q_, 128>>>(feat1, conf1, conf2, aflow, out);

    dim3 gg(MPAD / 128, MPAD / 128);
    k_gemm<<<gg, 256>>>(out);
}